// round 13
// baseline (speedup 1.0000x reference)
#include <cuda_runtime.h>

#define NVV   1024
#define VMAXF 6.0f
#define WPB   4                      // warps (rows) per CTA
#define PADN  (NVV + NVV / 32)       // +1 pad word per 32 -> conflict-free

__device__ __forceinline__ float frcp(float x) {
    float y;
    asm("rcp.approx.f32 %0, %1;" : "=f"(y) : "f"(x));
    return y;
}

// ---- packed f32x2 helpers (Blackwell FFMA2/FMUL2/FADD2 via PTX) -----------
typedef unsigned long long pf2;
__device__ __forceinline__ pf2 pack2(float lo, float hi) {
    pf2 r; asm("mov.b64 %0,{%1,%2};" : "=l"(r) : "f"(lo), "f"(hi)); return r;
}
__device__ __forceinline__ void unpack2(pf2 v, float& lo, float& hi) {
    asm("mov.b64 {%0,%1},%2;" : "=f"(lo), "=f"(hi) : "l"(v));
}
__device__ __forceinline__ pf2 bcast2(float x) { return pack2(x, x); }
__device__ __forceinline__ pf2 fma2(pf2 a, pf2 b, pf2 c) {
    pf2 d; asm("fma.rn.f32x2 %0,%1,%2,%3;" : "=l"(d) : "l"(a), "l"(b), "l"(c)); return d;
}
__device__ __forceinline__ pf2 mul2(pf2 a, pf2 b) {
    pf2 d; asm("mul.rn.f32x2 %0,%1,%2;" : "=l"(d) : "l"(a), "l"(b)); return d;
}
__device__ __forceinline__ pf2 add2(pf2 a, pf2 b) {
    pf2 d; asm("add.rn.f32x2 %0,%1,%2;" : "=l"(d) : "l"(a), "l"(b)); return d;
}

// ---------------------------------------------------------------------------
// Fused warp-per-row Fokker-Planck implicit step (SPIKE + 3-step PCR).
// Phase 3: single-pass scaled-continuant Thomas elimination with PRESCALED
// coefficients (As = A*invsig, Bs = B*invsig emitted directly by the packed
// pipeline) and a direct prefix product u = prod(cpn) for the SPIKE sums.
// ---------------------------------------------------------------------------
__global__ void __launch_bounds__(32 * WPB, 6) fp_fused(
    const float* __restrict__ f,
    const float* __restrict__ p_dv,
    const float* __restrict__ p_nu,
    const float* __restrict__ p_dt,
    float* __restrict__ out,
    int Brows)
{
    __shared__ float sF[WPB][PADN];   // f -> dq -> x
    __shared__ float sC[WPB][PADN];   // cpn
    const int warp = threadIdx.x >> 5;
    const int lane = threadIdx.x & 31;
    const int row  = blockIdx.x * WPB + warp;
    if (row >= Brows) return;          // warp-uniform

    const float dv = __ldg(p_dv), nu = __ldg(p_nu), dt = __ldg(p_dt);
    const float4* f4 = reinterpret_cast<const float4*>(f + (size_t)row * NVV);

    float* pT  = sF[warp] + 4 * lane + (lane >> 3);   // transpose pattern
    float* pF  = sF[warp] + 33 * lane;                // own-cell pattern
    float* pC  = sC[warp] + 33 * lane;

    // ---- Phase 1: coalesced load -> smem transpose + packed raw moments ----
    pf2 sfp = 0ull, sfvp = 0ull, sfv2p = 0ull;
    {
        float v0 = fmaf(dv, 4.0f * (float)lane + 0.5f, -VMAXF);
        pf2 vp01 = pack2(v0, v0 + dv);
        pf2 vp23 = add2(vp01, bcast2(2.0f * dv));
        const pf2 vadv = bcast2(128.0f * dv);
#pragma unroll
        for (int k = 0; k < 8; k++) {
            float4 fr = f4[lane + 32 * k];
            pf2 f01 = pack2(fr.x, fr.y);
            pf2 f23 = pack2(fr.z, fr.w);
            sfp   = add2(sfp, add2(f01, f23));
            sfvp  = fma2(f01, vp01, sfvp);
            sfvp  = fma2(f23, vp23, sfvp);
            pf2 fv01 = mul2(f01, vp01);
            pf2 fv23 = mul2(f23, vp23);
            sfv2p = fma2(fv01, vp01, sfv2p);
            sfv2p = fma2(fv23, vp23, sfv2p);
            pT[132 * k + 0] = fr.x;
            pT[132 * k + 1] = fr.y;
            pT[132 * k + 2] = fr.z;
            pT[132 * k + 3] = fr.w;
            vp01 = add2(vp01, vadv);
            vp23 = add2(vp23, vadv);
        }
    }
    __syncwarp();

    float sf, sfv, sfv2;
    {
        float a, b;
        unpack2(sfp, a, b);   sf   = a + b;
        unpack2(sfvp, a, b);  sfv  = a + b;
        unpack2(sfv2p, a, b); sfv2 = a + b;
    }
#pragma unroll
    for (int o = 16; o > 0; o >>= 1) {
        sf   += __shfl_xor_sync(0xffffffffu, sf,   o);
        sfv  += __shfl_xor_sync(0xffffffffu, sfv,  o);
        sfv2 += __shfl_xor_sync(0xffffffffu, sfv2, o);
    }
    float vbar = sfv / sf;
    float n    = sf * dv;
    float e_t  = dv * fmaf(-vbar, sfv, sfv2);   // dv * sum f (v-vbar)^2
    float noet = n / e_t;
    float beta = 0.5f * noet;
    const float dv2 = dv * dv;

    const int   j0 = lane * 32;
    const float u0 = fmaf(dv, (float)j0 + 0.5f, -VMAXF) - vbar;

    // ---- Phase 2: self-consistent beta, packed even/odd Gaussian walk ------
    const float u0sq = u0 * u0;
    const float c1   = dv * (2.0f * u0 + dv);
    const pf2 up0    = pack2(u0, u0 + dv);
    const pf2 du2    = bcast2(2.0f * dv);
    for (int it = 0; it < 10; it++) {
        float M0 = __expf(-beta * u0sq);
        float t0 = __expf(-beta * c1);
        float r  = __expf(-2.0f * beta * dv2);
        float r2 = r * r;
        float t0sq = t0 * t0;
        float T00  = t0sq * r;
        pf2 Mp = pack2(M0, M0 * t0);
        pf2 Tp = pack2(T00, T00 * r2);
        pf2 R4 = bcast2(r2 * r2);
        pf2 sMp = 0ull, sMup = 0ull;
        pf2 up = up0;
#pragma unroll
        for (int i = 0; i < 16; i++) {
            sMp = add2(sMp, Mp);
            pf2 Mu = mul2(Mp, up);
            sMup = fma2(Mu, up, sMup);
            Mp = mul2(Mp, Tp);
            Tp = mul2(Tp, R4);
            up = add2(up, du2);
        }
        float a, b, sM, sMu;
        unpack2(sMp, a, b);  sM  = a + b;
        unpack2(sMup, a, b); sMu = a + b;
#pragma unroll
        for (int o = 16; o > 0; o >>= 1) {
            sM  += __shfl_xor_sync(0xffffffffu, sM,  o);
            sMu += __shfl_xor_sync(0xffffffffu, sMu, o);
        }
        float ed = sMu / sM;
        float bn = beta * ed * noet;
        float diff = fabsf(bn - beta);
        beta = bn;
        if (diff <= 1e-6f * fabsf(bn)) break;
    }

    // ---- Phase 3 setup: Chang-Cooper coefficients --------------------------
    const float D    = 1.0f / (2.0f * beta);
    const float tbd  = 2.0f * beta * D;       // tracks reference rounding (~1)
    const float s    = dt * nu / dv;
    const float stbd = s * tbd;
    const float gs   = s * (D / dv);
    const float cA   = stbd * dv;
    const float cB   = -stbd * (VMAXF + vbar);
    const float kk   = (dv / D) / s;          // w = Ces * kk

    // lower edge of cell 0 (edge 0 flux-masked on lane 0)
    float CesL = (lane > 0) ? fmaf(cA, (float)j0, cB) : 0.f;
    float gsL  = (lane > 0) ? gs : 0.f;
    float wL   = CesL * kk;
    float wL2  = wL * wL;
    float dLo  = 0.5f + wL * (-(1.f / 12.f) + wL2 * (1.f / 720.f));
    const float Alo0 = fmaf(CesL, dLo, -gsL);
    const float Blo0 = CesL - Alo0;
    const float dl0  = Alo0;                  // unscaled, for xP coupling

    // scaling: sigma = power of two near dm_typ = 1 + 2 gs (exact rcp)
    unsigned int sb = __float_as_uint(1.0f + 2.0f * gs) & 0xFF800000u;
    const float sigf    = __uint_as_float(sb);
    const float invsig  = __uint_as_float((254u - (sb >> 23)) << 23);

    // packed constants; coefficient pipeline emits PRESCALED As/Bs directly:
    //   CesS = Ces*invsig tracked; w = CesS*(kk*sig); As = CesS*delta - gs*invsig
    const float kks   = kk * sigf;
    const pf2 kks2    = bcast2(kks);
    const pf2 c720    = bcast2(1.f / 720.f);
    const pf2 c12n    = bcast2(-(1.f / 12.f));
    const pf2 halfP   = bcast2(0.5f);
    const pf2 gssn2   = bcast2(-(gs * invsig));
    const pf2 neg1    = bcast2(-1.0f);
    const float cAs   = cA * invsig;
    const pf2 cesAdvS = bcast2(2.0f * cAs);
    const float Ces0s = fmaf(cA, (float)(j0 + 1), cB) * invsig;

    // ---- Phase 3: single-pass scaled-continuant elimination ---------------
    //   qh_i = dms_i*qh_{i-1} + (Aslo*Bslo)*qh_{i-2}   (the only chain FMA)
    //   dms = invsig + Bslo - Asup ; everything else off-chain
    float ev[32];
    float D0a = 0.f, Ea = 0.f;
    float q2 = 0.f, q1 = 1.f;
    float Rh = 0.f, St = 1.f, uac = 1.f;
    float cpnl = 0.f, dql = 0.f;
    float Aslo = Alo0 * invsig, Bslo = Blo0 * invsig;
    pf2 CesS = pack2(Ces0s, Ces0s + cAs);     // edges j0+2p+1, j0+2p+2 (scaled)

#pragma unroll
    for (int p = 0; p < 16; p++) {
        pf2 wP  = mul2(CesS, kks2);
        pf2 wwP = mul2(wP, wP);
        pf2 t   = fma2(wwP, c720, c12n);
        pf2 dUP = fma2(wP, t, halfP);
        pf2 AsP = fma2(CesS, dUP, gssn2);     // As = (Ce*delta - g)*invsig
        pf2 BsP = fma2(AsP, neg1, CesS);      // Bs = (Ce - A)*invsig
        float As0, As1, Bs0, Bs1;
        unpack2(AsP, As0, As1);
        unpack2(BsP, Bs0, Bs1);
        if (p == 15 && lane == 31) { As1 = 0.f; Bs1 = 0.f; }   // edge NVV mask
#pragma unroll
        for (int c = 0; c < 2; c++) {
            const int i = 2 * p + c;
            const float Asup = c ? As1 : As0;
            const float Bsup = c ? Bs1 : Bs0;
            float dms = (invsig + Bslo) - Asup;
            float tq  = (Aslo * Bslo) * q2;
            float q   = fmaf(dms, q1, tq);    // the only chain FMA
            float ic  = frcp(q);
            float ics = ic * invsig;
            if (i > 0) St = -Aslo * St;
            float cpn = (Bsup * q1) * ic;
            pC[i] = cpn;
            float fi = pF[i];
            Rh = fmaf(-Aslo, Rh, fi * q1);
            float dqi = Rh * ics;
            pF[i] = dqi;
            float evv = St * ics;
            ev[i] = evv;
            D0a = fmaf(uac, dqi, D0a);
            Ea  = fmaf(uac, evv, Ea);
            uac = uac * cpn;
            q2 = q1; q1 = q;
            Aslo = Asup; Bslo = Bsup;
            cpnl = cpn; dql = dqi;
        }
        CesS = add2(CesS, cesAdvS);
    }

    // reduced interface equations per lane p:
    //   x0(p) = D0 - A0*xL(p-1) - C0*x0(p+1)
    //   xL(p) = DL - AL*xL(p-1) - CL*x0(p+1)
    float D0  = D0a,  A0  = dl0 * Ea,      C0  = -uac;
    float DLc = dql,  ALc = dl0 * ev[31],  CLc = -cpnl;

    // ---- Phase 4: 3-step PCR on the 2x2-per-lane interface system ----------
    // couplings contract by the long-range factor (~0.02) each step:
    // after 3 steps max |coupling| < 1e-9 -> read x0=D0, xL=DL directly.
#pragma unroll
    for (int st = 1; st <= 4; st <<= 1) {
        float DLm = __shfl_up_sync(0xffffffffu, DLc, st);
        float ALm = __shfl_up_sync(0xffffffffu, ALc, st);
        float CLm = __shfl_up_sync(0xffffffffu, CLc, st);
        float D0p = __shfl_down_sync(0xffffffffu, D0, st);
        float A0p = __shfl_down_sync(0xffffffffu, A0, st);
        float C0p = __shfl_down_sync(0xffffffffu, C0, st);
        if (lane < st)      { DLm = 0.f; ALm = 0.f; CLm = 0.f; }
        if (lane + st > 31) { D0p = 0.f; A0p = 0.f; C0p = 0.f; }

        float a11 = fmaf(-A0,  CLm, 1.f);
        float a12 = C0  * A0p;                // actual a12 = -this
        float a21 = ALc * CLm;                // actual a21 = -this
        float a22 = fmaf(-CLc, A0p, 1.f);
        float r1  = fmaf(-C0,  D0p, fmaf(-A0,  DLm, D0));
        float r2  = fmaf(-CLc, D0p, fmaf(-ALc, DLm, DLc));
        float e1  = A0  * ALm, f1 = C0  * C0p;
        float e2  = ALc * ALm, f2 = CLc * C0p;
        float idet = frcp(fmaf(-a12, a21, a11 * a22));

        float nD0 =  idet * fmaf(a12, r2, a22 * r1);
        float nA0 = -idet * fmaf(a12, e2, a22 * e1);
        float nC0 = -idet * fmaf(a12, f2, a22 * f1);
        float nDL =  idet * fmaf(a21, r1, a11 * r2);
        float nAL = -idet * fmaf(a21, e1, a11 * e2);
        float nCL = -idet * fmaf(a21, f1, a11 * f2);
        D0 = nD0; A0 = nA0; C0 = nC0; DLc = nDL; ALc = nAL; CLc = nCL;
    }
    // direct readout: x0(p) = D0, xL(p) = DLc (residual couplings < 1e-9)
    float xN = __shfl_down_sync(0xffffffffu, D0, 1);
    if (lane == 31) xN = 0.f;
    float xP = __shfl_up_sync(0xffffffffu, DLc, 1);
    if (lane == 0)  xP = 0.f;

    // ---- Phase 5: per-lane backward substitution ---------------------------
    float K = dl0 * xP;
    float x = xN;                              // x_{j0+32}
#pragma unroll
    for (int i = 31; i >= 0; i--) {
        float dqi = fmaf(-K, ev[i], pF[i]);
        x = fmaf(pC[i], x, dqi);               // x_i = dq_eff + cpn*x_{i+1}
        pF[i] = x;
    }
    __syncwarp();

    float4* o4 = reinterpret_cast<float4*>(out + (size_t)row * NVV);
#pragma unroll
    for (int k = 0; k < 8; k++) {
        float4 o;
        o.x = pT[132 * k + 0];
        o.y = pT[132 * k + 1];
        o.z = pT[132 * k + 2];
        o.w = pT[132 * k + 3];
        o4[lane + 32 * k] = o;
    }
}

// ---------------------------------------------------------------------------
extern "C" void kernel_launch(void* const* d_in, const int* in_sizes, int n_in,
                              void* d_out, int out_size)
{
    const float* f    = (const float*)d_in[0];
    // d_in[1]=v, d_in[2]=v_edge: uniform grid, recomputed exactly in-kernel
    // (dv = 3*2^-8; all edge/center values exactly representable).
    const float* p_dv = (const float*)d_in[3];
    const float* p_nu = (const float*)d_in[4];
    const float* p_dt = (const float*)d_in[5];
    float* out = (float*)d_out;

    int Brows = in_sizes[0] / NVV;
    int grid = (Brows + WPB - 1) / WPB;
    fp_fused<<<grid, 32 * WPB>>>(f, p_dv, p_nu, p_dt, out, Brows);
}

// round 15
// speedup vs baseline: 1.2995x; 1.2995x over previous
#include <cuda_runtime.h>

#define NVV   1024
#define VMAXF 6.0f
#define WPB   4                      // warps (rows) per CTA
#define PADN  (NVV + NVV / 32)       // +1 pad word per 32 -> conflict-free

__device__ __forceinline__ float frcp(float x) {
    float y;
    asm("rcp.approx.f32 %0, %1;" : "=f"(y) : "f"(x));
    return y;
}

// ---- packed f32x2 helpers (Blackwell FFMA2/FMUL2/FADD2 via PTX) -----------
typedef unsigned long long pf2;
__device__ __forceinline__ pf2 pack2(float lo, float hi) {
    pf2 r; asm("mov.b64 %0,{%1,%2};" : "=l"(r) : "f"(lo), "f"(hi)); return r;
}
__device__ __forceinline__ void unpack2(pf2 v, float& lo, float& hi) {
    asm("mov.b64 {%0,%1},%2;" : "=f"(lo), "=f"(hi) : "l"(v));
}
__device__ __forceinline__ pf2 bcast2(float x) { return pack2(x, x); }
__device__ __forceinline__ pf2 fma2(pf2 a, pf2 b, pf2 c) {
    pf2 d; asm("fma.rn.f32x2 %0,%1,%2,%3;" : "=l"(d) : "l"(a), "l"(b), "l"(c)); return d;
}
__device__ __forceinline__ pf2 mul2(pf2 a, pf2 b) {
    pf2 d; asm("mul.rn.f32x2 %0,%1,%2;" : "=l"(d) : "l"(a), "l"(b)); return d;
}
__device__ __forceinline__ pf2 add2(pf2 a, pf2 b) {
    pf2 d; asm("add.rn.f32x2 %0,%1,%2;" : "=l"(d) : "l"(a), "l"(b)); return d;
}

// ---------------------------------------------------------------------------
// Fused warp-per-row Fokker-Planck implicit step (SPIKE + 3-step PCR).
// Phase 3: single-pass scaled-continuant Thomas elimination with PRESCALED
// coefficients (As = A*invsig, Bs = B*invsig emitted directly by the packed
// pipeline) and a direct prefix product u = prod(cpn) for the SPIKE sums.
// 5 CTAs/SM: the spill-free regime (6 forced ev[] to local -> 30% slower).
// ---------------------------------------------------------------------------
__global__ void __launch_bounds__(32 * WPB, 5) fp_fused(
    const float* __restrict__ f,
    const float* __restrict__ p_dv,
    const float* __restrict__ p_nu,
    const float* __restrict__ p_dt,
    float* __restrict__ out,
    int Brows)
{
    __shared__ float sF[WPB][PADN];   // f -> dq -> x
    __shared__ float sC[WPB][PADN];   // cpn
    const int warp = threadIdx.x >> 5;
    const int lane = threadIdx.x & 31;
    const int row  = blockIdx.x * WPB + warp;
    if (row >= Brows) return;          // warp-uniform

    const float dv = __ldg(p_dv), nu = __ldg(p_nu), dt = __ldg(p_dt);
    const float4* f4 = reinterpret_cast<const float4*>(f + (size_t)row * NVV);

    float* pT  = sF[warp] + 4 * lane + (lane >> 3);   // transpose pattern
    float* pF  = sF[warp] + 33 * lane;                // own-cell pattern
    float* pC  = sC[warp] + 33 * lane;

    // ---- Phase 1: coalesced load -> smem transpose + packed raw moments ----
    pf2 sfp = 0ull, sfvp = 0ull, sfv2p = 0ull;
    {
        float v0 = fmaf(dv, 4.0f * (float)lane + 0.5f, -VMAXF);
        pf2 vp01 = pack2(v0, v0 + dv);
        pf2 vp23 = add2(vp01, bcast2(2.0f * dv));
        const pf2 vadv = bcast2(128.0f * dv);
#pragma unroll
        for (int k = 0; k < 8; k++) {
            float4 fr = f4[lane + 32 * k];
            pf2 f01 = pack2(fr.x, fr.y);
            pf2 f23 = pack2(fr.z, fr.w);
            sfp   = add2(sfp, add2(f01, f23));
            sfvp  = fma2(f01, vp01, sfvp);
            sfvp  = fma2(f23, vp23, sfvp);
            pf2 fv01 = mul2(f01, vp01);
            pf2 fv23 = mul2(f23, vp23);
            sfv2p = fma2(fv01, vp01, sfv2p);
            sfv2p = fma2(fv23, vp23, sfv2p);
            pT[132 * k + 0] = fr.x;
            pT[132 * k + 1] = fr.y;
            pT[132 * k + 2] = fr.z;
            pT[132 * k + 3] = fr.w;
            vp01 = add2(vp01, vadv);
            vp23 = add2(vp23, vadv);
        }
    }
    __syncwarp();

    float sf, sfv, sfv2;
    {
        float a, b;
        unpack2(sfp, a, b);   sf   = a + b;
        unpack2(sfvp, a, b);  sfv  = a + b;
        unpack2(sfv2p, a, b); sfv2 = a + b;
    }
#pragma unroll
    for (int o = 16; o > 0; o >>= 1) {
        sf   += __shfl_xor_sync(0xffffffffu, sf,   o);
        sfv  += __shfl_xor_sync(0xffffffffu, sfv,  o);
        sfv2 += __shfl_xor_sync(0xffffffffu, sfv2, o);
    }
    float vbar = sfv / sf;
    float n    = sf * dv;
    float e_t  = dv * fmaf(-vbar, sfv, sfv2);   // dv * sum f (v-vbar)^2
    float noet = n / e_t;
    float beta = 0.5f * noet;
    const float dv2 = dv * dv;

    const int   j0 = lane * 32;
    const float u0 = fmaf(dv, (float)j0 + 0.5f, -VMAXF) - vbar;

    // ---- Phase 2: self-consistent beta, packed even/odd Gaussian walk ------
    const float u0sq = u0 * u0;
    const float c1   = dv * (2.0f * u0 + dv);
    const pf2 up0    = pack2(u0, u0 + dv);
    const pf2 du2    = bcast2(2.0f * dv);
    for (int it = 0; it < 10; it++) {
        float M0 = __expf(-beta * u0sq);
        float t0 = __expf(-beta * c1);
        float r  = __expf(-2.0f * beta * dv2);
        float r2 = r * r;
        float t0sq = t0 * t0;
        float T00  = t0sq * r;
        pf2 Mp = pack2(M0, M0 * t0);
        pf2 Tp = pack2(T00, T00 * r2);
        pf2 R4 = bcast2(r2 * r2);
        pf2 sMp = 0ull, sMup = 0ull;
        pf2 up = up0;
#pragma unroll
        for (int i = 0; i < 16; i++) {
            sMp = add2(sMp, Mp);
            pf2 Mu = mul2(Mp, up);
            sMup = fma2(Mu, up, sMup);
            Mp = mul2(Mp, Tp);
            Tp = mul2(Tp, R4);
            up = add2(up, du2);
        }
        float a, b, sM, sMu;
        unpack2(sMp, a, b);  sM  = a + b;
        unpack2(sMup, a, b); sMu = a + b;
#pragma unroll
        for (int o = 16; o > 0; o >>= 1) {
            sM  += __shfl_xor_sync(0xffffffffu, sM,  o);
            sMu += __shfl_xor_sync(0xffffffffu, sMu, o);
        }
        float ed = sMu / sM;
        float bn = beta * ed * noet;
        float diff = fabsf(bn - beta);
        beta = bn;
        if (diff <= 1e-6f * fabsf(bn)) break;
    }

    // ---- Phase 3 setup: Chang-Cooper coefficients --------------------------
    const float D    = 1.0f / (2.0f * beta);
    const float tbd  = 2.0f * beta * D;       // tracks reference rounding (~1)
    const float s    = dt * nu / dv;
    const float stbd = s * tbd;
    const float gs   = s * (D / dv);
    const float cA   = stbd * dv;
    const float cB   = -stbd * (VMAXF + vbar);
    const float kk   = (dv / D) / s;          // w = Ces * kk

    // lower edge of cell 0 (edge 0 flux-masked on lane 0)
    float CesL = (lane > 0) ? fmaf(cA, (float)j0, cB) : 0.f;
    float gsL  = (lane > 0) ? gs : 0.f;
    float wL   = CesL * kk;
    float wL2  = wL * wL;
    float dLo  = 0.5f + wL * (-(1.f / 12.f) + wL2 * (1.f / 720.f));
    const float Alo0 = fmaf(CesL, dLo, -gsL);
    const float Blo0 = CesL - Alo0;
    const float dl0  = Alo0;                  // unscaled, for xP coupling

    // scaling: sigma = power of two near dm_typ = 1 + 2 gs (exact rcp)
    unsigned int sb = __float_as_uint(1.0f + 2.0f * gs) & 0xFF800000u;
    const float sigf    = __uint_as_float(sb);
    const float invsig  = __uint_as_float((254u - (sb >> 23)) << 23);

    // packed constants; coefficient pipeline emits PRESCALED As/Bs directly:
    //   CesS = Ces*invsig tracked; w = CesS*(kk*sig); As = CesS*delta - gs*invsig
    const float kks   = kk * sigf;
    const pf2 kks2    = bcast2(kks);
    const pf2 c720    = bcast2(1.f / 720.f);
    const pf2 c12n    = bcast2(-(1.f / 12.f));
    const pf2 halfP   = bcast2(0.5f);
    const pf2 gssn2   = bcast2(-(gs * invsig));
    const pf2 neg1    = bcast2(-1.0f);
    const float cAs   = cA * invsig;
    const pf2 cesAdvS = bcast2(2.0f * cAs);
    const float Ces0s = fmaf(cA, (float)(j0 + 1), cB) * invsig;

    // ---- Phase 3: single-pass scaled-continuant elimination ---------------
    //   qh_i = dms_i*qh_{i-1} + (Aslo*Bslo)*qh_{i-2}   (the only chain FMA)
    //   dms = invsig + Bslo - Asup ; everything else off-chain
    float ev[32];
    float D0a = 0.f, Ea = 0.f;
    float q2 = 0.f, q1 = 1.f;
    float Rh = 0.f, St = 1.f, uac = 1.f;
    float cpnl = 0.f, dql = 0.f;
    float Aslo = Alo0 * invsig, Bslo = Blo0 * invsig;
    pf2 CesS = pack2(Ces0s, Ces0s + cAs);     // edges j0+2p+1, j0+2p+2 (scaled)

#pragma unroll
    for (int p = 0; p < 16; p++) {
        pf2 wP  = mul2(CesS, kks2);
        pf2 wwP = mul2(wP, wP);
        pf2 t   = fma2(wwP, c720, c12n);
        pf2 dUP = fma2(wP, t, halfP);
        pf2 AsP = fma2(CesS, dUP, gssn2);     // As = (Ce*delta - g)*invsig
        pf2 BsP = fma2(AsP, neg1, CesS);      // Bs = (Ce - A)*invsig
        float As0, As1, Bs0, Bs1;
        unpack2(AsP, As0, As1);
        unpack2(BsP, Bs0, Bs1);
        if (p == 15 && lane == 31) { As1 = 0.f; Bs1 = 0.f; }   // edge NVV mask
#pragma unroll
        for (int c = 0; c < 2; c++) {
            const int i = 2 * p + c;
            const float Asup = c ? As1 : As0;
            const float Bsup = c ? Bs1 : Bs0;
            float dms = (invsig + Bslo) - Asup;
            float tq  = (Aslo * Bslo) * q2;
            float q   = fmaf(dms, q1, tq);    // the only chain FMA
            float ic  = frcp(q);
            float ics = ic * invsig;
            if (i > 0) St = -Aslo * St;
            float cpn = (Bsup * q1) * ic;
            pC[i] = cpn;
            float fi = pF[i];
            Rh = fmaf(-Aslo, Rh, fi * q1);
            float dqi = Rh * ics;
            pF[i] = dqi;
            float evv = St * ics;
            ev[i] = evv;
            D0a = fmaf(uac, dqi, D0a);
            Ea  = fmaf(uac, evv, Ea);
            uac = uac * cpn;
            q2 = q1; q1 = q;
            Aslo = Asup; Bslo = Bsup;
            cpnl = cpn; dql = dqi;
        }
        CesS = add2(CesS, cesAdvS);
    }

    // reduced interface equations per lane p:
    //   x0(p) = D0 - A0*xL(p-1) - C0*x0(p+1)
    //   xL(p) = DL - AL*xL(p-1) - CL*x0(p+1)
    float D0  = D0a,  A0  = dl0 * Ea,      C0  = -uac;
    float DLc = dql,  ALc = dl0 * ev[31],  CLc = -cpnl;

    // ---- Phase 4: 3-step PCR on the 2x2-per-lane interface system ----------
    // couplings contract by the long-range factor (~0.02) each step:
    // after 3 steps max |coupling| < 1e-9 -> read x0=D0, xL=DL directly.
#pragma unroll
    for (int st = 1; st <= 4; st <<= 1) {
        float DLm = __shfl_up_sync(0xffffffffu, DLc, st);
        float ALm = __shfl_up_sync(0xffffffffu, ALc, st);
        float CLm = __shfl_up_sync(0xffffffffu, CLc, st);
        float D0p = __shfl_down_sync(0xffffffffu, D0, st);
        float A0p = __shfl_down_sync(0xffffffffu, A0, st);
        float C0p = __shfl_down_sync(0xffffffffu, C0, st);
        if (lane < st)      { DLm = 0.f; ALm = 0.f; CLm = 0.f; }
        if (lane + st > 31) { D0p = 0.f; A0p = 0.f; C0p = 0.f; }

        float a11 = fmaf(-A0,  CLm, 1.f);
        float a12 = C0  * A0p;                // actual a12 = -this
        float a21 = ALc * CLm;                // actual a21 = -this
        float a22 = fmaf(-CLc, A0p, 1.f);
        float r1  = fmaf(-C0,  D0p, fmaf(-A0,  DLm, D0));
        float r2  = fmaf(-CLc, D0p, fmaf(-ALc, DLm, DLc));
        float e1  = A0  * ALm, f1 = C0  * C0p;
        float e2  = ALc * ALm, f2 = CLc * C0p;
        float idet = frcp(fmaf(-a12, a21, a11 * a22));

        float nD0 =  idet * fmaf(a12, r2, a22 * r1);
        float nA0 = -idet * fmaf(a12, e2, a22 * e1);
        float nC0 = -idet * fmaf(a12, f2, a22 * f1);
        float nDL =  idet * fmaf(a21, r1, a11 * r2);
        float nAL = -idet * fmaf(a21, e1, a11 * e2);
        float nCL = -idet * fmaf(a21, f1, a11 * f2);
        D0 = nD0; A0 = nA0; C0 = nC0; DLc = nDL; ALc = nAL; CLc = nCL;
    }
    // direct readout: x0(p) = D0, xL(p) = DLc (residual couplings < 1e-9)
    float xN = __shfl_down_sync(0xffffffffu, D0, 1);
    if (lane == 31) xN = 0.f;
    float xP = __shfl_up_sync(0xffffffffu, DLc, 1);
    if (lane == 0)  xP = 0.f;

    // ---- Phase 5: per-lane backward substitution ---------------------------
    float K = dl0 * xP;
    float x = xN;                              // x_{j0+32}
#pragma unroll
    for (int i = 31; i >= 0; i--) {
        float dqi = fmaf(-K, ev[i], pF[i]);
        x = fmaf(pC[i], x, dqi);               // x_i = dq_eff + cpn*x_{i+1}
        pF[i] = x;
    }
    __syncwarp();

    float4* o4 = reinterpret_cast<float4*>(out + (size_t)row * NVV);
#pragma unroll
    for (int k = 0; k < 8; k++) {
        float4 o;
        o.x = pT[132 * k + 0];
        o.y = pT[132 * k + 1];
        o.z = pT[132 * k + 2];
        o.w = pT[132 * k + 3];
        o4[lane + 32 * k] = o;
    }
}

// ---------------------------------------------------------------------------
extern "C" void kernel_launch(void* const* d_in, const int* in_sizes, int n_in,
                              void* d_out, int out_size)
{
    const float* f    = (const float*)d_in[0];
    // d_in[1]=v, d_in[2]=v_edge: uniform grid, recomputed exactly in-kernel
    // (dv = 3*2^-8; all edge/center values exactly representable).
    const float* p_dv = (const float*)d_in[3];
    const float* p_nu = (const float*)d_in[4];
    const float* p_dt = (const float*)d_in[5];
    float* out = (float*)d_out;

    int Brows = in_sizes[0] / NVV;
    int grid = (Brows + WPB - 1) / WPB;
    fp_fused<<<grid, 32 * WPB>>>(f, p_dv, p_nu, p_dt, out, Brows);
}